// round 1
// baseline (speedup 1.0000x reference)
#include <cuda_runtime.h>
#include <cuda_bf16.h>
#include <math.h>

// Problem shape (fixed by the dataset):
//   B=64, T=512, D_in=256, D_out=1024, M=8 (module_size=128)
// Inputs (metadata order): x[B,T,Din], W_in[Din,Dout], b_in[Dout],
//                          W_h[Dout,Dout], periods[M], shifts[M]
// Output: ys[B,T,Dout] (33554432 floats) then h_final[B,Dout] (65536 floats)
//
// Strategy:
//   Phase 1 (parallel):  u = x@W_in + b_in written directly into the ys region
//                        of d_out ([B*T, 1024] row-major == ys layout).
//   Phase 2 (persistent, 128 CTAs, software grid barrier):
//       for t: h_prev = ys[:,t-1,:] (zeros at t=0)
//              acts   = tanh(u(:,t,:) + h_prev @ W_h)
//              ys[:,t,:] = (1-gate)*acts + gate*h_prev   (overwrites u in place)
//       then copy ys[:,T-1,:] -> h_final.

#define B_      64
#define T_      512
#define DIN     256
#define DOUT    1024
#define BSTR    ((size_t)T_ * DOUT)      // per-batch stride in floats (524288)
#define YS_ELEMS ((size_t)B_ * T_ * DOUT)

// ---------------------------------------------------------------------------
// Phase 1: u = X @ W_in + b_in     (M=32768, N=1024, K=256)
// Tile 128x64 per CTA, 256 threads, 8x4 microtile, K-chunks of 16.
// ---------------------------------------------------------------------------
__global__ void __launch_bounds__(256) phase1_gemm(
    const float* __restrict__ X, const float* __restrict__ Win,
    const float* __restrict__ bin, float* __restrict__ out)
{
    __shared__ float As[16 * 132];   // As[k][m], padded row stride 132
    __shared__ float Bs[16 * 68];    // Bs[k][n], padded row stride 68

    const int tid = threadIdx.x;
    const int tn0 = blockIdx.x * 64;
    const int tm0 = blockIdx.y * 128;
    const int ty  = tid >> 4;        // 0..15 -> 8 rows each
    const int tx  = tid & 15;        // 0..15 -> 4 cols each

    float acc[8][4];
#pragma unroll
    for (int i = 0; i < 8; i++)
#pragma unroll
        for (int j = 0; j < 4; j++) acc[i][j] = 0.f;

    const int arow  = tid >> 1;          // 0..127
    const int akoff = (tid & 1) * 8;     // 0 or 8
    const int bk    = tid >> 4;          // 0..15
    const int bn    = (tid & 15) * 4;    // 0..60

    for (int kc = 0; kc < DIN; kc += 16) {
        const float* ap = &X[(size_t)(tm0 + arow) * DIN + kc + akoff];
        float4 a0 = *(const float4*)(ap);
        float4 a1 = *(const float4*)(ap + 4);
        float4 b0 = *(const float4*)&Win[(size_t)(kc + bk) * DOUT + tn0 + bn];

        __syncthreads();   // previous chunk's compute done before overwrite
        As[(akoff + 0) * 132 + arow] = a0.x;
        As[(akoff + 1) * 132 + arow] = a0.y;
        As[(akoff + 2) * 132 + arow] = a0.z;
        As[(akoff + 3) * 132 + arow] = a0.w;
        As[(akoff + 4) * 132 + arow] = a1.x;
        As[(akoff + 5) * 132 + arow] = a1.y;
        As[(akoff + 6) * 132 + arow] = a1.z;
        As[(akoff + 7) * 132 + arow] = a1.w;
        *(float4*)&Bs[bk * 68 + bn] = b0;
        __syncthreads();

#pragma unroll
        for (int kk = 0; kk < 16; kk++) {
            float4 af0 = *(const float4*)&As[kk * 132 + ty * 8];
            float4 af1 = *(const float4*)&As[kk * 132 + ty * 8 + 4];
            float4 bf  = *(const float4*)&Bs[kk * 68 + tx * 4];
            float a[8] = {af0.x, af0.y, af0.z, af0.w, af1.x, af1.y, af1.z, af1.w};
            float b[4] = {bf.x, bf.y, bf.z, bf.w};
#pragma unroll
            for (int i = 0; i < 8; i++)
#pragma unroll
                for (int j = 0; j < 4; j++)
                    acc[i][j] = fmaf(a[i], b[j], acc[i][j]);
        }
    }

    float4 bias = *(const float4*)&bin[tn0 + tx * 4];
#pragma unroll
    for (int i = 0; i < 8; i++) {
        float4 r;
        r.x = acc[i][0] + bias.x;
        r.y = acc[i][1] + bias.y;
        r.z = acc[i][2] + bias.z;
        r.w = acc[i][3] + bias.w;
        *(float4*)&out[(size_t)(tm0 + ty * 8 + i) * DOUT + tn0 + tx * 4] = r;
    }
}

// ---------------------------------------------------------------------------
// Phase 2: persistent recurrence. 128 CTAs x 256 threads, 8 cols per CTA.
// ---------------------------------------------------------------------------
#define NB2 128

__device__ unsigned g_count = 0;
__device__ volatile unsigned g_gen = 0;

// Grid barrier. Monotonic targets within a run; "!= target" spin makes it
// safe across graph replays without resetting g_gen.
__device__ __forceinline__ void gsync(unsigned target)
{
    __syncthreads();
    if (threadIdx.x == 0) {
        __threadfence();                         // publish this CTA's writes
        if (atomicAdd(&g_count, 1u) == NB2 - 1) {
            g_count = 0;
            __threadfence();
            g_gen = target;                      // release
        } else {
            while (g_gen != target) { }          // spin (L2 hit poll)
            __threadfence();                     // acquire
        }
    }
    __syncthreads();
}

__global__ void __launch_bounds__(256) phase2_rnn(
    const float* __restrict__ Wh, const float* __restrict__ periods,
    const float* __restrict__ shifts, float* __restrict__ out)
{
    __shared__ float sW[DOUT * 8];   // W_h columns j0..j0+7, layout sW[k*8+jj]
    __shared__ float sH[32 * 65];    // h chunk transposed: sH[k][row], pad 65

    const int tid = threadIdx.x;
    const int bid = blockIdx.x;
    const int j0  = bid * 8;

    // Preload this CTA's 8 W_h columns (one-time, 32 KB)
    for (int i = tid; i < DOUT * 8; i += 256)
        sW[i] = Wh[(size_t)(i >> 3) * DOUT + j0 + (i & 7)];

    const float per = periods[j0 >> 7];
    const float shf = shifts[j0 >> 7];

    const int w   = tid >> 5;
    const int l   = tid & 31;
    const int cp  = (w & 3) * 2;             // column pair within tile
    const int row = ((w >> 2) << 5) + l;     // batch index 0..63
    const int lrow = tid >> 2;               // staging: row 0..63
    const int koff = (tid & 3) * 8;          // staging: k offset 0/8/16/24

    __syncthreads();

    for (int t = 0; t < T_; t++) {
        float acc0 = 0.f, acc1 = 0.f;
        for (int kc = 0; kc < DOUT; kc += 32) {
            float v[8];
            if (t > 0) {
                const float* p = out + (size_t)lrow * BSTR
                                     + (size_t)(t - 1) * DOUT + kc + koff;
                float4 u0 = *(const float4*)p;
                float4 u1 = *(const float4*)(p + 4);
                v[0] = u0.x; v[1] = u0.y; v[2] = u0.z; v[3] = u0.w;
                v[4] = u1.x; v[5] = u1.y; v[6] = u1.z; v[7] = u1.w;
            } else {
#pragma unroll
                for (int m = 0; m < 8; m++) v[m] = 0.f;
            }
            __syncthreads();   // previous chunk consumed
#pragma unroll
            for (int m = 0; m < 8; m++)
                sH[(koff + m) * 65 + lrow] = v[m];
            __syncthreads();
#pragma unroll
            for (int kk = 0; kk < 32; kk++) {
                float h = sH[kk * 65 + row];
                float2 wv = *(const float2*)&sW[((kc + kk) << 3) + cp];
                acc0 = fmaf(h, wv.x, acc0);
                acc1 = fmaf(h, wv.y, acc1);
            }
        }

        // Epilogue: read pre-stored u, apply tanh + gate, overwrite with y.
        const size_t ob = (size_t)row * BSTR + (size_t)t * DOUT + j0 + cp;
        float2 u = *(const float2*)&out[ob];
        float2 hp = make_float2(0.f, 0.f);
        if (t > 0) hp = *(const float2*)&out[ob - DOUT];
        float g = (sinf((float)t * per + shf) + 1.f) * 0.5f;
        float a0 = tanhf(u.x + acc0);
        float a1 = tanhf(u.y + acc1);
        float2 y;
        y.x = (1.f - g) * a0 + g * hp.x;
        y.y = (1.f - g) * a1 + g * hp.y;
        *(float2*)&out[ob] = y;

        gsync((unsigned)(t + 1));
    }

    // h_final = ys[:, T-1, :]
    for (int idx = bid * 256 + tid; idx < B_ * DOUT; idx += NB2 * 256) {
        int b = idx >> 10, j = idx & (DOUT - 1);
        out[YS_ELEMS + idx] = out[(size_t)b * BSTR + (size_t)(T_ - 1) * DOUT + j];
    }
}

// ---------------------------------------------------------------------------
extern "C" void kernel_launch(void* const* d_in, const int* in_sizes, int n_in,
                              void* d_out, int out_size)
{
    (void)in_sizes; (void)n_in; (void)out_size;
    const float* x       = (const float*)d_in[0];
    const float* W_in    = (const float*)d_in[1];
    const float* b_in    = (const float*)d_in[2];
    const float* W_h     = (const float*)d_in[3];
    const float* periods = (const float*)d_in[4];
    const float* shifts  = (const float*)d_in[5];
    float* out = (float*)d_out;

    dim3 g1(DOUT / 64, (B_ * T_) / 128);       // (16, 256)
    phase1_gemm<<<g1, 256>>>(x, W_in, b_in, out);
    phase2_rnn<<<NB2, 256>>>(W_h, periods, shifts, out);
}

// round 2
// speedup vs baseline: 1.0009x; 1.0009x over previous
#include <cuda_runtime.h>
#include <cuda_bf16.h>
#include <math.h>

// Problem shape (fixed by the dataset):
//   B=64, T=512, D_in=256, D_out=1024, M=8 (module_size=128)
// Inputs (metadata order): x[B,T,Din], W_in[Din,Dout], b_in[Dout],
//                          W_h[Dout,Dout], periods[M], shifts[M]
// Output: ys[B,T,Dout] (33554432 floats) then h_final[B,Dout] (65536 floats)
//
// Strategy:
//   Phase 1 (parallel):  u = x@W_in + b_in written directly into the ys region
//                        of d_out ([B*T, 1024] row-major == ys layout).
//   Phase 2 (persistent, 128 CTAs, software grid barrier):
//       for t: h_prev = ys[:,t-1,:] (zeros at t=0)
//              acts   = tanh(u(:,t,:) + h_prev @ W_h)
//              ys[:,t,:] = (1-gate)*acts + gate*h_prev   (overwrites u in place)
//       then copy ys[:,T-1,:] -> h_final.

#define B_      64
#define T_      512
#define DIN     256
#define DOUT    1024
#define BSTR    ((size_t)T_ * DOUT)      // per-batch stride in floats (524288)
#define YS_ELEMS ((size_t)B_ * T_ * DOUT)

// ---------------------------------------------------------------------------
// Phase 1: u = X @ W_in + b_in     (M=32768, N=1024, K=256)
// Tile 128x64 per CTA, 256 threads, 8x4 microtile, K-chunks of 16.
// ---------------------------------------------------------------------------
__global__ void __launch_bounds__(256) phase1_gemm(
    const float* __restrict__ X, const float* __restrict__ Win,
    const float* __restrict__ bin, float* __restrict__ out)
{
    __shared__ float As[16 * 132];   // As[k][m], padded row stride 132
    __shared__ float Bs[16 * 68];    // Bs[k][n], padded row stride 68

    const int tid = threadIdx.x;
    const int tn0 = blockIdx.x * 64;
    const int tm0 = blockIdx.y * 128;
    const int ty  = tid >> 4;        // 0..15 -> 8 rows each
    const int tx  = tid & 15;        // 0..15 -> 4 cols each

    float acc[8][4];
#pragma unroll
    for (int i = 0; i < 8; i++)
#pragma unroll
        for (int j = 0; j < 4; j++) acc[i][j] = 0.f;

    const int arow  = tid >> 1;          // 0..127
    const int akoff = (tid & 1) * 8;     // 0 or 8
    const int bk    = tid >> 4;          // 0..15
    const int bn    = (tid & 15) * 4;    // 0..60

    for (int kc = 0; kc < DIN; kc += 16) {
        const float* ap = &X[(size_t)(tm0 + arow) * DIN + kc + akoff];
        float4 a0 = *(const float4*)(ap);
        float4 a1 = *(const float4*)(ap + 4);
        float4 b0 = *(const float4*)&Win[(size_t)(kc + bk) * DOUT + tn0 + bn];

        __syncthreads();   // previous chunk's compute done before overwrite
        As[(akoff + 0) * 132 + arow] = a0.x;
        As[(akoff + 1) * 132 + arow] = a0.y;
        As[(akoff + 2) * 132 + arow] = a0.z;
        As[(akoff + 3) * 132 + arow] = a0.w;
        As[(akoff + 4) * 132 + arow] = a1.x;
        As[(akoff + 5) * 132 + arow] = a1.y;
        As[(akoff + 6) * 132 + arow] = a1.z;
        As[(akoff + 7) * 132 + arow] = a1.w;
        *(float4*)&Bs[bk * 68 + bn] = b0;
        __syncthreads();

#pragma unroll
        for (int kk = 0; kk < 16; kk++) {
            float4 af0 = *(const float4*)&As[kk * 132 + ty * 8];
            float4 af1 = *(const float4*)&As[kk * 132 + ty * 8 + 4];
            float4 bf  = *(const float4*)&Bs[kk * 68 + tx * 4];
            float a[8] = {af0.x, af0.y, af0.z, af0.w, af1.x, af1.y, af1.z, af1.w};
            float b[4] = {bf.x, bf.y, bf.z, bf.w};
#pragma unroll
            for (int i = 0; i < 8; i++)
#pragma unroll
                for (int j = 0; j < 4; j++)
                    acc[i][j] = fmaf(a[i], b[j], acc[i][j]);
        }
    }

    float4 bias = *(const float4*)&bin[tn0 + tx * 4];
#pragma unroll
    for (int i = 0; i < 8; i++) {
        float4 r;
        r.x = acc[i][0] + bias.x;
        r.y = acc[i][1] + bias.y;
        r.z = acc[i][2] + bias.z;
        r.w = acc[i][3] + bias.w;
        *(float4*)&out[(size_t)(tm0 + ty * 8 + i) * DOUT + tn0 + tx * 4] = r;
    }
}

// ---------------------------------------------------------------------------
// Phase 2: persistent recurrence. 128 CTAs x 256 threads, 8 cols per CTA.
// ---------------------------------------------------------------------------
#define NB2 128

__device__ unsigned g_count = 0;
__device__ volatile unsigned g_gen = 0;

// Grid barrier. Monotonic targets within a run; "!= target" spin makes it
// safe across graph replays without resetting g_gen.
__device__ __forceinline__ void gsync(unsigned target)
{
    __syncthreads();
    if (threadIdx.x == 0) {
        __threadfence();                         // publish this CTA's writes
        if (atomicAdd(&g_count, 1u) == NB2 - 1) {
            g_count = 0;
            __threadfence();
            g_gen = target;                      // release
        } else {
            while (g_gen != target) { }          // spin (L2 hit poll)
            __threadfence();                     // acquire
        }
    }
    __syncthreads();
}

__global__ void __launch_bounds__(256) phase2_rnn(
    const float* __restrict__ Wh, const float* __restrict__ periods,
    const float* __restrict__ shifts, float* __restrict__ out)
{
    __shared__ float sW[DOUT * 8];   // W_h columns j0..j0+7, layout sW[k*8+jj]
    __shared__ float sH[32 * 65];    // h chunk transposed: sH[k][row], pad 65

    const int tid = threadIdx.x;
    const int bid = blockIdx.x;
    const int j0  = bid * 8;

    // Preload this CTA's 8 W_h columns (one-time, 32 KB)
    for (int i = tid; i < DOUT * 8; i += 256)
        sW[i] = Wh[(size_t)(i >> 3) * DOUT + j0 + (i & 7)];

    const float per = periods[j0 >> 7];
    const float shf = shifts[j0 >> 7];

    const int w   = tid >> 5;
    const int l   = tid & 31;
    const int cp  = (w & 3) * 2;             // column pair within tile
    const int row = ((w >> 2) << 5) + l;     // batch index 0..63
    const int lrow = tid >> 2;               // staging: row 0..63
    const int koff = (tid & 3) * 8;          // staging: k offset 0/8/16/24

    __syncthreads();

    for (int t = 0; t < T_; t++) {
        float acc0 = 0.f, acc1 = 0.f;
        for (int kc = 0; kc < DOUT; kc += 32) {
            float v[8];
            if (t > 0) {
                const float* p = out + (size_t)lrow * BSTR
                                     + (size_t)(t - 1) * DOUT + kc + koff;
                float4 u0 = *(const float4*)p;
                float4 u1 = *(const float4*)(p + 4);
                v[0] = u0.x; v[1] = u0.y; v[2] = u0.z; v[3] = u0.w;
                v[4] = u1.x; v[5] = u1.y; v[6] = u1.z; v[7] = u1.w;
            } else {
#pragma unroll
                for (int m = 0; m < 8; m++) v[m] = 0.f;
            }
            __syncthreads();   // previous chunk consumed
#pragma unroll
            for (int m = 0; m < 8; m++)
                sH[(koff + m) * 65 + lrow] = v[m];
            __syncthreads();
#pragma unroll
            for (int kk = 0; kk < 32; kk++) {
                float h = sH[kk * 65 + row];
                float2 wv = *(const float2*)&sW[((kc + kk) << 3) + cp];
                acc0 = fmaf(h, wv.x, acc0);
                acc1 = fmaf(h, wv.y, acc1);
            }
        }

        // Epilogue: read pre-stored u, apply tanh + gate, overwrite with y.
        const size_t ob = (size_t)row * BSTR + (size_t)t * DOUT + j0 + cp;
        float2 u = *(const float2*)&out[ob];
        float2 hp = make_float2(0.f, 0.f);
        if (t > 0) hp = *(const float2*)&out[ob - DOUT];
        float g = (sinf((float)t * per + shf) + 1.f) * 0.5f;
        float a0 = tanhf(u.x + acc0);
        float a1 = tanhf(u.y + acc1);
        float2 y;
        y.x = (1.f - g) * a0 + g * hp.x;
        y.y = (1.f - g) * a1 + g * hp.y;
        *(float2*)&out[ob] = y;

        gsync((unsigned)(t + 1));
    }

    // h_final = ys[:, T-1, :]
    for (int idx = bid * 256 + tid; idx < B_ * DOUT; idx += NB2 * 256) {
        int b = idx >> 10, j = idx & (DOUT - 1);
        out[YS_ELEMS + idx] = out[(size_t)b * BSTR + (size_t)(T_ - 1) * DOUT + j];
    }
}

// ---------------------------------------------------------------------------
extern "C" void kernel_launch(void* const* d_in, const int* in_sizes, int n_in,
                              void* d_out, int out_size)
{
    (void)in_sizes; (void)n_in; (void)out_size;
    const float* x       = (const float*)d_in[0];
    const float* W_in    = (const float*)d_in[1];
    const float* b_in    = (const float*)d_in[2];
    const float* W_h     = (const float*)d_in[3];
    const float* periods = (const float*)d_in[4];
    const float* shifts  = (const float*)d_in[5];
    float* out = (float*)d_out;

    dim3 g1(DOUT / 64, (B_ * T_) / 128);       // (16, 256)
    phase1_gemm<<<g1, 256>>>(x, W_in, b_in, out);
    phase2_rnn<<<NB2, 256>>>(W_h, periods, shifts, out);
}

// round 3
// speedup vs baseline: 1.0011x; 1.0001x over previous
#include <cuda_runtime.h>
#include <cuda_bf16.h>
#include <math.h>

// Problem shape (fixed by the dataset):
//   B=64, T=512, D_in=256, D_out=1024, M=8 (module_size=128)
// Inputs (metadata order): x[B,T,Din], W_in[Din,Dout], b_in[Dout],
//                          W_h[Dout,Dout], periods[M], shifts[M]
// Output: ys[B,T,Dout] (33554432 floats) then h_final[B,Dout] (65536 floats)
//
// Strategy:
//   Phase 1 (parallel):  u = x@W_in + b_in written directly into the ys region
//                        of d_out ([B*T, 1024] row-major == ys layout).
//   Phase 2 (persistent, 128 CTAs, software grid barrier):
//       for t: h_prev = ys[:,t-1,:] (zeros at t=0)
//              acts   = tanh(u(:,t,:) + h_prev @ W_h)
//              ys[:,t,:] = (1-gate)*acts + gate*h_prev   (overwrites u in place)
//       then copy ys[:,T-1,:] -> h_final.

#define B_      64
#define T_      512
#define DIN     256
#define DOUT    1024
#define BSTR    ((size_t)T_ * DOUT)      // per-batch stride in floats (524288)
#define YS_ELEMS ((size_t)B_ * T_ * DOUT)

// ---------------------------------------------------------------------------
// Phase 1: u = X @ W_in + b_in     (M=32768, N=1024, K=256)
// Tile 128x64 per CTA, 256 threads, 8x4 microtile, K-chunks of 16.
// ---------------------------------------------------------------------------
__global__ void __launch_bounds__(256) phase1_gemm(
    const float* __restrict__ X, const float* __restrict__ Win,
    const float* __restrict__ bin, float* __restrict__ out)
{
    __shared__ float As[16 * 132];   // As[k][m], padded row stride 132
    __shared__ float Bs[16 * 68];    // Bs[k][n], padded row stride 68

    const int tid = threadIdx.x;
    const int tn0 = blockIdx.x * 64;
    const int tm0 = blockIdx.y * 128;
    const int ty  = tid >> 4;        // 0..15 -> 8 rows each
    const int tx  = tid & 15;        // 0..15 -> 4 cols each

    float acc[8][4];
#pragma unroll
    for (int i = 0; i < 8; i++)
#pragma unroll
        for (int j = 0; j < 4; j++) acc[i][j] = 0.f;

    const int arow  = tid >> 1;          // 0..127
    const int akoff = (tid & 1) * 8;     // 0 or 8
    const int bk    = tid >> 4;          // 0..15
    const int bn    = (tid & 15) * 4;    // 0..60

    for (int kc = 0; kc < DIN; kc += 16) {
        const float* ap = &X[(size_t)(tm0 + arow) * DIN + kc + akoff];
        float4 a0 = *(const float4*)(ap);
        float4 a1 = *(const float4*)(ap + 4);
        float4 b0 = *(const float4*)&Win[(size_t)(kc + bk) * DOUT + tn0 + bn];

        __syncthreads();   // previous chunk's compute done before overwrite
        As[(akoff + 0) * 132 + arow] = a0.x;
        As[(akoff + 1) * 132 + arow] = a0.y;
        As[(akoff + 2) * 132 + arow] = a0.z;
        As[(akoff + 3) * 132 + arow] = a0.w;
        As[(akoff + 4) * 132 + arow] = a1.x;
        As[(akoff + 5) * 132 + arow] = a1.y;
        As[(akoff + 6) * 132 + arow] = a1.z;
        As[(akoff + 7) * 132 + arow] = a1.w;
        *(float4*)&Bs[bk * 68 + bn] = b0;
        __syncthreads();

#pragma unroll
        for (int kk = 0; kk < 16; kk++) {
            float4 af0 = *(const float4*)&As[kk * 132 + ty * 8];
            float4 af1 = *(const float4*)&As[kk * 132 + ty * 8 + 4];
            float4 bf  = *(const float4*)&Bs[kk * 68 + tx * 4];
            float a[8] = {af0.x, af0.y, af0.z, af0.w, af1.x, af1.y, af1.z, af1.w};
            float b[4] = {bf.x, bf.y, bf.z, bf.w};
#pragma unroll
            for (int i = 0; i < 8; i++)
#pragma unroll
                for (int j = 0; j < 4; j++)
                    acc[i][j] = fmaf(a[i], b[j], acc[i][j]);
        }
    }

    float4 bias = *(const float4*)&bin[tn0 + tx * 4];
#pragma unroll
    for (int i = 0; i < 8; i++) {
        float4 r;
        r.x = acc[i][0] + bias.x;
        r.y = acc[i][1] + bias.y;
        r.z = acc[i][2] + bias.z;
        r.w = acc[i][3] + bias.w;
        *(float4*)&out[(size_t)(tm0 + ty * 8 + i) * DOUT + tn0 + tx * 4] = r;
    }
}

// ---------------------------------------------------------------------------
// Phase 2: persistent recurrence. 128 CTAs x 256 threads, 8 cols per CTA.
// ---------------------------------------------------------------------------
#define NB2 128

__device__ unsigned g_count = 0;
__device__ volatile unsigned g_gen = 0;

// Grid barrier. Monotonic targets within a run; "!= target" spin makes it
// safe across graph replays without resetting g_gen.
__device__ __forceinline__ void gsync(unsigned target)
{
    __syncthreads();
    if (threadIdx.x == 0) {
        __threadfence();                         // publish this CTA's writes
        if (atomicAdd(&g_count, 1u) == NB2 - 1) {
            g_count = 0;
            __threadfence();
            g_gen = target;                      // release
        } else {
            while (g_gen != target) { }          // spin (L2 hit poll)
            __threadfence();                     // acquire
        }
    }
    __syncthreads();
}

__global__ void __launch_bounds__(256) phase2_rnn(
    const float* __restrict__ Wh, const float* __restrict__ periods,
    const float* __restrict__ shifts, float* __restrict__ out)
{
    __shared__ float sW[DOUT * 8];   // W_h columns j0..j0+7, layout sW[k*8+jj]
    __shared__ float sH[32 * 65];    // h chunk transposed: sH[k][row], pad 65

    const int tid = threadIdx.x;
    const int bid = blockIdx.x;
    const int j0  = bid * 8;

    // Preload this CTA's 8 W_h columns (one-time, 32 KB)
    for (int i = tid; i < DOUT * 8; i += 256)
        sW[i] = Wh[(size_t)(i >> 3) * DOUT + j0 + (i & 7)];

    const float per = periods[j0 >> 7];
    const float shf = shifts[j0 >> 7];

    const int w   = tid >> 5;
    const int l   = tid & 31;
    const int cp  = (w & 3) * 2;             // column pair within tile
    const int row = ((w >> 2) << 5) + l;     // batch index 0..63
    const int lrow = tid >> 2;               // staging: row 0..63
    const int koff = (tid & 3) * 8;          // staging: k offset 0/8/16/24

    __syncthreads();

    for (int t = 0; t < T_; t++) {
        float acc0 = 0.f, acc1 = 0.f;
        for (int kc = 0; kc < DOUT; kc += 32) {
            float v[8];
            if (t > 0) {
                const float* p = out + (size_t)lrow * BSTR
                                     + (size_t)(t - 1) * DOUT + kc + koff;
                float4 u0 = *(const float4*)p;
                float4 u1 = *(const float4*)(p + 4);
                v[0] = u0.x; v[1] = u0.y; v[2] = u0.z; v[3] = u0.w;
                v[4] = u1.x; v[5] = u1.y; v[6] = u1.z; v[7] = u1.w;
            } else {
#pragma unroll
                for (int m = 0; m < 8; m++) v[m] = 0.f;
            }
            __syncthreads();   // previous chunk consumed
#pragma unroll
            for (int m = 0; m < 8; m++)
                sH[(koff + m) * 65 + lrow] = v[m];
            __syncthreads();
#pragma unroll
            for (int kk = 0; kk < 32; kk++) {
                float h = sH[kk * 65 + row];
                float2 wv = *(const float2*)&sW[((kc + kk) << 3) + cp];
                acc0 = fmaf(h, wv.x, acc0);
                acc1 = fmaf(h, wv.y, acc1);
            }
        }

        // Epilogue: read pre-stored u, apply tanh + gate, overwrite with y.
        const size_t ob = (size_t)row * BSTR + (size_t)t * DOUT + j0 + cp;
        float2 u = *(const float2*)&out[ob];
        float2 hp = make_float2(0.f, 0.f);
        if (t > 0) hp = *(const float2*)&out[ob - DOUT];
        float g = (sinf((float)t * per + shf) + 1.f) * 0.5f;
        float a0 = tanhf(u.x + acc0);
        float a1 = tanhf(u.y + acc1);
        float2 y;
        y.x = (1.f - g) * a0 + g * hp.x;
        y.y = (1.f - g) * a1 + g * hp.y;
        *(float2*)&out[ob] = y;

        gsync((unsigned)(t + 1));
    }

    // h_final = ys[:, T-1, :]
    for (int idx = bid * 256 + tid; idx < B_ * DOUT; idx += NB2 * 256) {
        int b = idx >> 10, j = idx & (DOUT - 1);
        out[YS_ELEMS + idx] = out[(size_t)b * BSTR + (size_t)(T_ - 1) * DOUT + j];
    }
}

// ---------------------------------------------------------------------------
extern "C" void kernel_launch(void* const* d_in, const int* in_sizes, int n_in,
                              void* d_out, int out_size)
{
    (void)in_sizes; (void)n_in; (void)out_size;
    const float* x       = (const float*)d_in[0];
    const float* W_in    = (const float*)d_in[1];
    const float* b_in    = (const float*)d_in[2];
    const float* W_h     = (const float*)d_in[3];
    const float* periods = (const float*)d_in[4];
    const float* shifts  = (const float*)d_in[5];
    float* out = (float*)d_out;

    dim3 g1(DOUT / 64, (B_ * T_) / 128);       // (16, 256)
    phase1_gemm<<<g1, 256>>>(x, W_in, b_in, out);
    phase2_rnn<<<NB2, 256>>>(W_h, periods, shifts, out);
}

// round 4
// speedup vs baseline: 2.0314x; 2.0292x over previous
#include <cuda_runtime.h>
#include <cuda_bf16.h>
#include <math.h>

// Problem shape (fixed by the dataset):
//   B=64, T=512, D_in=256, D_out=1024, M=8 (module_size=128)
// Inputs: x[B,T,Din], W_in[Din,Dout], b_in[Dout], W_h[Dout,Dout],
//         periods[M], shifts[M]
// Output: ys[B,T,Dout] (33554432 floats) then h_final[B,Dout].
//
// Phase 1: u = x@W_in + b_in written into the ys region of d_out (packed-fp32 GEMM).
// Phase 2: persistent 128-CTA recurrence; h broadcast via a transposed
//          double-buffered __device__ scratch (g_hT), mainloop = coalesced
//          LDG.64 (.cg) + fma.rn.f32x2, 8-way split-K with smem reduction.

#define B_      64
#define T_      512
#define DIN     256
#define DOUT    1024
#define BSTR    ((size_t)T_ * DOUT)
#define YS_ELEMS ((size_t)B_ * T_ * DOUT)

typedef unsigned long long ull;

// ---------------------------------------------------------------------------
// Packed-fp32 helpers (Blackwell f32x2)
// ---------------------------------------------------------------------------
__device__ __forceinline__ ull dupf(float x) {
    ull r;
    asm("mov.b64 %0, {%1, %1};" : "=l"(r) : "f"(x));
    return r;
}
__device__ __forceinline__ void ffma2(ull& d, ull a, ull b) {
    asm("fma.rn.f32x2 %0, %1, %2, %0;" : "+l"(d) : "l"(a), "l"(b));
}
__device__ __forceinline__ ull addf2(ull a, ull b) {
    ull r;
    asm("add.rn.f32x2 %0, %1, %2;" : "=l"(r) : "l"(a), "l"(b));
    return r;
}
__device__ __forceinline__ float2 unpk(ull v) {
    float2 r;
    asm("mov.b64 {%0, %1}, %2;" : "=f"(r.x), "=f"(r.y) : "l"(v));
    return r;
}

// ---------------------------------------------------------------------------
// Phase 1: u = X @ W_in + b_in     (M=32768, N=1024, K=256)
// Tile 128x64 per CTA, 256 threads, 8x4 microtile (cols packed f32x2).
// ---------------------------------------------------------------------------
__global__ void __launch_bounds__(256) phase1_gemm(
    const float* __restrict__ X, const float* __restrict__ Win,
    const float* __restrict__ bin, float* __restrict__ out)
{
    __shared__ float As[16 * 132];   // As[k][m], padded row stride 132
    __shared__ float Bs[16 * 68];    // Bs[k][n], padded row stride 68 (272B rows, 16B-aligned)

    const int tid = threadIdx.x;
    const int tn0 = blockIdx.x * 64;
    const int tm0 = blockIdx.y * 128;
    const int ty  = tid >> 4;        // 0..15 -> 8 rows each
    const int tx  = tid & 15;        // 0..15 -> 4 cols each

    ull acc01[8], acc23[8];
#pragma unroll
    for (int i = 0; i < 8; i++) { acc01[i] = 0ull; acc23[i] = 0ull; }

    const int arow  = tid >> 1;
    const int akoff = (tid & 1) * 8;
    const int bk    = tid >> 4;
    const int bn    = (tid & 15) * 4;

    for (int kc = 0; kc < DIN; kc += 16) {
        const float* ap = &X[(size_t)(tm0 + arow) * DIN + kc + akoff];
        float4 a0 = *(const float4*)(ap);
        float4 a1 = *(const float4*)(ap + 4);
        float4 b0 = *(const float4*)&Win[(size_t)(kc + bk) * DOUT + tn0 + bn];

        __syncthreads();
        As[(akoff + 0) * 132 + arow] = a0.x;
        As[(akoff + 1) * 132 + arow] = a0.y;
        As[(akoff + 2) * 132 + arow] = a0.z;
        As[(akoff + 3) * 132 + arow] = a0.w;
        As[(akoff + 4) * 132 + arow] = a1.x;
        As[(akoff + 5) * 132 + arow] = a1.y;
        As[(akoff + 6) * 132 + arow] = a1.z;
        As[(akoff + 7) * 132 + arow] = a1.w;
        *(float4*)&Bs[bk * 68 + bn] = b0;
        __syncthreads();

#pragma unroll
        for (int kk = 0; kk < 16; kk++) {
            float4 af0 = *(const float4*)&As[kk * 132 + ty * 8];
            float4 af1 = *(const float4*)&As[kk * 132 + ty * 8 + 4];
            ulonglong2 bb = *(const ulonglong2*)&Bs[kk * 68 + tx * 4];
            float a[8] = {af0.x, af0.y, af0.z, af0.w, af1.x, af1.y, af1.z, af1.w};
#pragma unroll
            for (int i = 0; i < 8; i++) {
                ull ad = dupf(a[i]);
                ffma2(acc01[i], ad, bb.x);
                ffma2(acc23[i], ad, bb.y);
            }
        }
    }

    ulonglong2 bp = *(const ulonglong2*)&bin[tn0 + tx * 4];
#pragma unroll
    for (int i = 0; i < 8; i++) {
        ulonglong2 st;
        st.x = addf2(acc01[i], bp.x);
        st.y = addf2(acc23[i], bp.y);
        *(ulonglong2*)&out[(size_t)(tm0 + ty * 8 + i) * DOUT + tn0 + tx * 4] = st;
    }
}

// ---------------------------------------------------------------------------
// Phase 2: persistent recurrence. 128 CTAs x 256 threads, 8 cols per CTA.
// ---------------------------------------------------------------------------
#define NB2 128

// Transposed hidden state, double-buffered by t parity: g_hT[buf][j][r].
__device__ float g_hT[2][DOUT * B_];

__device__ unsigned g_count = 0;
__device__ volatile unsigned g_gen = 0;

__device__ __forceinline__ void gsync(unsigned target)
{
    __syncthreads();
    if (threadIdx.x == 0) {
        __threadfence();
        if (atomicAdd(&g_count, 1u) == NB2 - 1) {
            g_count = 0;
            __threadfence();
            g_gen = target;                      // release
        } else {
            while (g_gen != target) { }          // spin (L2 poll)
            __threadfence();                     // acquire
        }
    }
    __syncthreads();
}

__global__ void __launch_bounds__(256) phase2_rnn(
    const float* __restrict__ Wh, const float* __restrict__ periods,
    const float* __restrict__ shifts, float* __restrict__ out)
{
    __shared__ float2 sW[DOUT * 4];      // [k][col-pair], 32 KB, constant over t
    __shared__ ull    sP[8 * 8 * 32];    // [w][slot][lane^ (slot<<1)], 16 KB

    const int tid = threadIdx.x;
    const int bid = blockIdx.x;
    const int j0  = bid * 8;
    const int w   = tid >> 5;            // warp = k-slice
    const int l   = tid & 31;            // lane -> rows (2l, 2l+1)

    // One-time: this CTA's 8 W_h columns as col-pairs.
    for (int i = tid; i < DOUT * 4; i += 256) {
        int k = i >> 2, cp = i & 3;
        sW[i] = make_float2(Wh[(size_t)k * DOUT + j0 + 2 * cp],
                            Wh[(size_t)k * DOUT + j0 + 2 * cp + 1]);
    }
    const float per = periods[bid >> 4];
    const float shf = shifts[bid >> 4];

    // Epilogue/reduction mapping: thread -> (row er, col-pair ecp).
    const int er   = tid >> 2;           // 0..63
    const int ecp  = tid & 3;            // 0..3
    const int ej   = j0 + 2 * ecp;
    const int sres = tid & 7;            // = (er&1)*4 + ecp
    const int rrow = tid >> 3;           // = er>>1
    __syncthreads();

    // ---- t = 0: h_prev = 0, so acts = tanh(u); gate mixes with 0. ----
    {
        float g = (sinf(shf) + 1.f) * 0.5f;
        size_t ob = (size_t)er * BSTR + ej;
        float2 u = *(const float2*)&out[ob];
        float2 y;
        y.x = (1.f - g) * tanhf(u.x);
        y.y = (1.f - g) * tanhf(u.y);
        *(float2*)&out[ob] = y;
        g_hT[0][ej * B_ + er]       = y.x;
        g_hT[0][(ej + 1) * B_ + er] = y.y;
        gsync(1u);
    }

    const int kbase = w << 7;            // warp's K-slice [128w, 128w+128)

    for (int t = 1; t < T_; t++) {
        const float* __restrict__ hsrc = g_hT[(t - 1) & 1];
        float*       __restrict__ hdst = g_hT[t & 1];

        ull a0 = 0, a1 = 0, a2 = 0, a3 = 0, a4 = 0, a5 = 0, a6 = 0, a7 = 0;

#pragma unroll 8
        for (int kk = 0; kk < 128; kk++) {
            const int k = kbase + kk;
            // h pair for rows (2l, 2l+1): coalesced 256B/warp, L2-coherent load.
            double hpd = __ldcg((const double*)&hsrc[(k << 6) + (l << 1)]);
            float hx = __int_as_float(__double2loint(hpd));
            float hy = __int_as_float(__double2hiint(hpd));
            ull hd0 = dupf(hx);
            ull hd1 = dupf(hy);
            const ulonglong2* wp = (const ulonglong2*)&sW[k << 2];
            ulonglong2 wA = wp[0];       // {c0c1, c2c3} (broadcast)
            ulonglong2 wB = wp[1];       // {c4c5, c6c7}
            ffma2(a0, hd0, wA.x); ffma2(a1, hd0, wA.y);
            ffma2(a2, hd0, wB.x); ffma2(a3, hd0, wB.y);
            ffma2(a4, hd1, wA.x); ffma2(a5, hd1, wA.y);
            ffma2(a6, hd1, wB.x); ffma2(a7, hd1, wB.y);
        }

        // Partials: slot s = rr*4 + cp; lane index XOR-swizzled by (s<<1).
#define STP(s, v) sP[((w << 3) + (s)) * 32 + (l ^ ((s) << 1))] = (v)
        STP(0, a0); STP(1, a1); STP(2, a2); STP(3, a3);
        STP(4, a4); STP(5, a5); STP(6, a6); STP(7, a7);
#undef STP
        __syncthreads();

        // 8-way cross-warp reduction + epilogue (one thread per (row, col-pair)).
        ull sum = sP[sres * 32 + (rrow ^ (sres << 1))];
#pragma unroll
        for (int w2 = 1; w2 < 8; w2++)
            sum = addf2(sum, sP[((w2 << 3) + sres) * 32 + (rrow ^ (sres << 1))]);
        float2 hv = unpk(sum);

        size_t ob = (size_t)er * BSTR + (size_t)t * DOUT + ej;
        float2 u = *(const float2*)&out[ob];
        float hpx = __ldcg(&hsrc[ej * B_ + er]);
        float hpy = __ldcg(&hsrc[(ej + 1) * B_ + er]);
        float g = (sinf((float)t * per + shf) + 1.f) * 0.5f;
        float2 y;
        y.x = (1.f - g) * tanhf(u.x + hv.x) + g * hpx;
        y.y = (1.f - g) * tanhf(u.y + hv.y) + g * hpy;
        *(float2*)&out[ob] = y;
        hdst[ej * B_ + er]       = y.x;
        hdst[(ej + 1) * B_ + er] = y.y;

        gsync((unsigned)(t + 1));        // also fences sP reuse
    }

    // h_final = ys[:, T-1, :]  (cross-CTA reads -> .cg)
    for (int idx = bid * 256 + tid; idx < B_ * DOUT; idx += NB2 * 256) {
        int b = idx >> 10, j = idx & (DOUT - 1);
        out[YS_ELEMS + idx] =
            __ldcg(&out[(size_t)b * BSTR + (size_t)(T_ - 1) * DOUT + j]);
    }
}

// ---------------------------------------------------------------------------
extern "C" void kernel_launch(void* const* d_in, const int* in_sizes, int n_in,
                              void* d_out, int out_size)
{
    (void)in_sizes; (void)n_in; (void)out_size;
    const float* x       = (const float*)d_in[0];
    const float* W_in    = (const float*)d_in[1];
    const float* b_in    = (const float*)d_in[2];
    const float* W_h     = (const float*)d_in[3];
    const float* periods = (const float*)d_in[4];
    const float* shifts  = (const float*)d_in[5];
    float* out = (float*)d_out;

    dim3 g1(DOUT / 64, (B_ * T_) / 128);       // (16, 256)
    phase1_gemm<<<g1, 256>>>(x, W_in, b_in, out);
    phase2_rnn<<<NB2, 256>>>(W_h, periods, shifts, out);
}

// round 6
// speedup vs baseline: 3.5762x; 1.7605x over previous
#include <cuda_runtime.h>
#include <cuda_bf16.h>
#include <math.h>

// Problem shape (fixed by the dataset):
//   B=64, T=512, D_in=256, D_out=1024, M=8 (module_size=128)
// Inputs: x[B,T,Din], W_in[Din,Dout], b_in[Dout], W_h[Dout,Dout],
//         periods[M], shifts[M]
// Output: ys[B,T,Dout] (33554432 floats) then h_final[B,Dout].
//
// Phase 1: u = x@W_in + b_in written into the ys region of d_out (f32x2 GEMM).
// Phase 2: persistent 128-CTA x 512-thread recurrence; transposed
//          double-buffered h scratch (g_hT); 16-way split-K, 8-deep LDG.cg
//          prefetch ring, fma.rn.f32x2 mainloop, flag-tree grid barrier.
//          64 KB DYNAMIC smem (sW 32K + sP 32K) via MaxDynamicSharedMemorySize.

#define B_      64
#define T_      512
#define DIN     256
#define DOUT    1024
#define BSTR    ((size_t)T_ * DOUT)
#define YS_ELEMS ((size_t)B_ * T_ * DOUT)

typedef unsigned long long ull;

// ---------------------------------------------------------------------------
// Packed-fp32 helpers (Blackwell f32x2)
// ---------------------------------------------------------------------------
__device__ __forceinline__ ull dupf(float x) {
    ull r;
    asm("mov.b64 %0, {%1, %1};" : "=l"(r) : "f"(x));
    return r;
}
__device__ __forceinline__ void ffma2(ull& d, ull a, ull b) {
    asm("fma.rn.f32x2 %0, %1, %2, %0;" : "+l"(d) : "l"(a), "l"(b));
}
__device__ __forceinline__ ull addf2(ull a, ull b) {
    ull r;
    asm("add.rn.f32x2 %0, %1, %2;" : "=l"(r) : "l"(a), "l"(b));
    return r;
}
__device__ __forceinline__ float2 unpk(ull v) {
    float2 r;
    asm("mov.b64 {%0, %1}, %2;" : "=f"(r.x), "=f"(r.y) : "l"(v));
    return r;
}
__device__ __forceinline__ ull duplo(ull v) {
    ull r;
    asm("{\n\t.reg .b32 a,b;\n\tmov.b64 {a,b}, %1;\n\tmov.b64 %0, {a,a};\n\t}"
        : "=l"(r) : "l"(v));
    return r;
}
__device__ __forceinline__ ull duphi(ull v) {
    ull r;
    asm("{\n\t.reg .b32 a,b;\n\tmov.b64 {a,b}, %1;\n\tmov.b64 %0, {b,b};\n\t}"
        : "=l"(r) : "l"(v));
    return r;
}
__device__ __forceinline__ ull ldcg_u64(const float* p) {
    ull r;
    asm volatile("ld.global.cg.b64 %0, [%1];" : "=l"(r) : "l"(p));
    return r;
}

// ---------------------------------------------------------------------------
// Phase 1: u = X @ W_in + b_in     (M=32768, N=1024, K=256)
// ---------------------------------------------------------------------------
__global__ void __launch_bounds__(256) phase1_gemm(
    const float* __restrict__ X, const float* __restrict__ Win,
    const float* __restrict__ bin, float* __restrict__ out)
{
    __shared__ float As[16 * 132];
    __shared__ float Bs[16 * 68];

    const int tid = threadIdx.x;
    const int tn0 = blockIdx.x * 64;
    const int tm0 = blockIdx.y * 128;
    const int ty  = tid >> 4;
    const int tx  = tid & 15;

    ull acc01[8], acc23[8];
#pragma unroll
    for (int i = 0; i < 8; i++) { acc01[i] = 0ull; acc23[i] = 0ull; }

    const int arow  = tid >> 1;
    const int akoff = (tid & 1) * 8;
    const int bk    = tid >> 4;
    const int bn    = (tid & 15) * 4;

    for (int kc = 0; kc < DIN; kc += 16) {
        const float* ap = &X[(size_t)(tm0 + arow) * DIN + kc + akoff];
        float4 a0 = *(const float4*)(ap);
        float4 a1 = *(const float4*)(ap + 4);
        float4 b0 = *(const float4*)&Win[(size_t)(kc + bk) * DOUT + tn0 + bn];

        __syncthreads();
        As[(akoff + 0) * 132 + arow] = a0.x;
        As[(akoff + 1) * 132 + arow] = a0.y;
        As[(akoff + 2) * 132 + arow] = a0.z;
        As[(akoff + 3) * 132 + arow] = a0.w;
        As[(akoff + 4) * 132 + arow] = a1.x;
        As[(akoff + 5) * 132 + arow] = a1.y;
        As[(akoff + 6) * 132 + arow] = a1.z;
        As[(akoff + 7) * 132 + arow] = a1.w;
        *(float4*)&Bs[bk * 68 + bn] = b0;
        __syncthreads();

#pragma unroll
        for (int kk = 0; kk < 16; kk++) {
            float4 af0 = *(const float4*)&As[kk * 132 + ty * 8];
            float4 af1 = *(const float4*)&As[kk * 132 + ty * 8 + 4];
            ulonglong2 bb = *(const ulonglong2*)&Bs[kk * 68 + tx * 4];
            float a[8] = {af0.x, af0.y, af0.z, af0.w, af1.x, af1.y, af1.z, af1.w};
#pragma unroll
            for (int i = 0; i < 8; i++) {
                ull ad = dupf(a[i]);
                ffma2(acc01[i], ad, bb.x);
                ffma2(acc23[i], ad, bb.y);
            }
        }
    }

    ulonglong2 bp = *(const ulonglong2*)&bin[tn0 + tx * 4];
#pragma unroll
    for (int i = 0; i < 8; i++) {
        ulonglong2 st;
        st.x = addf2(acc01[i], bp.x);
        st.y = addf2(acc23[i], bp.y);
        *(ulonglong2*)&out[(size_t)(tm0 + ty * 8 + i) * DOUT + tn0 + tx * 4] = st;
    }
}

// ---------------------------------------------------------------------------
// Phase 2: persistent recurrence. 128 CTAs x 512 threads, 8 cols per CTA.
// ---------------------------------------------------------------------------
#define NB2 128
#define NW2 16          // warps per CTA (k-slices)
#define KSL 64          // k per warp
#define SMEM2 (DOUT * 4 * 8 + NW2 * 8 * 32 * 8)   // 32 KB sW + 32 KB sP

// Transposed hidden state, double-buffered by t parity: g_hT[buf][j*64 + r].
__device__ float g_hT[2][DOUT * B_];

// Flag-tree grid barrier state. Per-CTA flags padded 128B apart.
__device__ volatile unsigned g_flag[NB2 * 32];
__device__ volatile unsigned g_gen2;

// Grid barrier: CTA stores its step to a private flag (no contention);
// CTA 0 warp 0 polls all flags and broadcasts via g_gen2. Equality
// comparisons + strictly increasing targets make this replay-safe (the only
// stale value, 512 from the previous replay, is first compared against 1).
__device__ __forceinline__ void gsync(int bid, unsigned target)
{
    __syncthreads();
    if (threadIdx.x < 32) {
        if (threadIdx.x == 0) {
            __threadfence();
            g_flag[bid << 5] = target;
        }
        if (bid == 0) {
            bool done;
            do {
                done = true;
#pragma unroll
                for (int c = threadIdx.x; c < NB2; c += 32)
                    if (g_flag[c << 5] != target) done = false;
            } while (!__all_sync(0xffffffffu, done));
            if (threadIdx.x == 0) {
                __threadfence();
                g_gen2 = target;
            }
        } else if (threadIdx.x == 0) {
            while (g_gen2 != target) { }
            __threadfence();
        }
    }
    __syncthreads();
}

__global__ void __launch_bounds__(512) phase2_rnn(
    const float* __restrict__ Wh, const float* __restrict__ periods,
    const float* __restrict__ shifts, float* __restrict__ out)
{
    extern __shared__ char smem_raw[];
    float2* sW = (float2*)smem_raw;                      // [k][col-pair], 32 KB
    ull*    sP = (ull*)(smem_raw + DOUT * 4 * 8);        // [w][slot][lane^..], 32 KB

    const int tid = threadIdx.x;
    const int bid = blockIdx.x;
    const int j0  = bid * 8;
    const int w   = tid >> 5;                // warp = k-slice (0..15)
    const int l   = tid & 31;                // lane -> rows (2l, 2l+1)

    // One-time: this CTA's 8 W_h columns as col-pairs.
    for (int i = tid; i < DOUT * 4; i += 512) {
        int k = i >> 2, cp = i & 3;
        sW[i] = make_float2(Wh[(size_t)k * DOUT + j0 + 2 * cp],
                            Wh[(size_t)k * DOUT + j0 + 2 * cp + 1]);
    }
    const float per = periods[bid >> 4];
    const float shf = shifts[bid >> 4];

    // Epilogue mapping (tid < 256): thread -> (row er, col-pair ecp).
    const int er   = (tid & 255) >> 2;       // 0..63
    const int ecp  = tid & 3;                // 0..3
    const int ej   = j0 + 2 * ecp;
    const int sres = ((er & 1) << 2) + ecp;  // slot 0..7
    const int rrow = er >> 1;                // 0..31
    __syncthreads();

    // ---- t = 0: h_prev = 0 -> y = (1-g) * tanh(u). ----
    if (tid < 256) {
        float g = (sinf(shf) + 1.f) * 0.5f;
        size_t ob = (size_t)er * BSTR + ej;
        float2 u = *(const float2*)&out[ob];
        float2 y;
        y.x = (1.f - g) * tanhf(u.x);
        y.y = (1.f - g) * tanhf(u.y);
        *(float2*)&out[ob] = y;
        g_hT[0][ej * B_ + er]       = y.x;
        g_hT[0][(ej + 1) * B_ + er] = y.y;
    }
    gsync(bid, 1u);

    const int kbase = w << 6;                // this warp's K-slice base

    for (int t = 1; t < T_; t++) {
        const float* __restrict__ hsrc = g_hT[(t - 1) & 1];
        float*       __restrict__ hdst = g_hT[t & 1];

        // Hoist epilogue loads so their latency hides under the mainloop.
        float2 uv = make_float2(0.f, 0.f), hpv = make_float2(0.f, 0.f);
        size_t ob = 0;
        if (tid < 256) {
            ob  = (size_t)er * BSTR + (size_t)t * DOUT + ej;
            uv  = *(const float2*)&out[ob];
            hpv.x = __ldcg(&hsrc[ej * B_ + er]);
            hpv.y = __ldcg(&hsrc[(ej + 1) * B_ + er]);
        }

        // Mainloop: 64 k per warp, 8-deep LDG.cg prefetch ring.
        const float* hs = hsrc + (kbase << 6) + (l << 1);
        ull a0 = 0, a1 = 0, a2 = 0, a3 = 0, a4 = 0, a5 = 0, a6 = 0, a7 = 0;
        ull hbuf[8];
#pragma unroll
        for (int j = 0; j < 8; j++) hbuf[j] = ldcg_u64(hs + (j << 6));

#pragma unroll
        for (int kk = 0; kk < KSL; kk += 8) {
#pragma unroll
            for (int j = 0; j < 8; j++) {
                ull hp = hbuf[j];
                const int knext = kk + 8 + j;
                if (knext < KSL) hbuf[j] = ldcg_u64(hs + (knext << 6));
                const ulonglong2* wp =
                    (const ulonglong2*)&sW[(kbase + kk + j) << 2];
                ulonglong2 wA = wp[0];       // {c0c1, c2c3} (broadcast)
                ulonglong2 wB = wp[1];       // {c4c5, c6c7}
                ull hd0 = duplo(hp);
                ull hd1 = duphi(hp);
                ffma2(a0, hd0, wA.x); ffma2(a1, hd0, wA.y);
                ffma2(a2, hd0, wB.x); ffma2(a3, hd0, wB.y);
                ffma2(a4, hd1, wA.x); ffma2(a5, hd1, wA.y);
                ffma2(a6, hd1, wB.x); ffma2(a7, hd1, wB.y);
            }
        }

        // Partials to smem: slot s = rr*4 + cp, lane XOR-swizzled by (s<<1).
#define STP(s, v) sP[((w << 3) + (s)) * 32 + (l ^ ((s) << 1))] = (v)
        STP(0, a0); STP(1, a1); STP(2, a2); STP(3, a3);
        STP(4, a4); STP(5, a5); STP(6, a6); STP(7, a7);
#undef STP
        __syncthreads();

        // 16-way cross-warp reduction + epilogue (tid < 256).
        if (tid < 256) {
            const int lx = rrow ^ (sres << 1);
            ull sum = sP[(sres << 5) + lx];
#pragma unroll
            for (int w2 = 1; w2 < NW2; w2++)
                sum = addf2(sum, sP[(((w2 << 3) + sres) << 5) + lx]);
            float2 hv = unpk(sum);

            float g = (sinf((float)t * per + shf) + 1.f) * 0.5f;
            float2 y;
            y.x = (1.f - g) * tanhf(uv.x + hv.x) + g * hpv.x;
            y.y = (1.f - g) * tanhf(uv.y + hv.y) + g * hpv.y;
            *(float2*)&out[ob] = y;
            hdst[ej * B_ + er]       = y.x;
            hdst[(ej + 1) * B_ + er] = y.y;
        }

        gsync(bid, (unsigned)(t + 1));       // also fences sP reuse
    }

    // h_final = ys[:, T-1, :]  (cross-CTA reads -> .cg)
    for (int idx = bid * 512 + tid; idx < B_ * DOUT; idx += NB2 * 512) {
        int b = idx >> 10, j = idx & (DOUT - 1);
        out[YS_ELEMS + idx] =
            __ldcg(&out[(size_t)b * BSTR + (size_t)(T_ - 1) * DOUT + j]);
    }
}

// ---------------------------------------------------------------------------
extern "C" void kernel_launch(void* const* d_in, const int* in_sizes, int n_in,
                              void* d_out, int out_size)
{
    (void)in_sizes; (void)n_in; (void)out_size;
    const float* x       = (const float*)d_in[0];
    const float* W_in    = (const float*)d_in[1];
    const float* b_in    = (const float*)d_in[2];
    const float* W_h     = (const float*)d_in[3];
    const float* periods = (const float*)d_in[4];
    const float* shifts  = (const float*)d_in[5];
    float* out = (float*)d_out;

    // Opt-in smem above 48 KB (function-state call: legal under capture,
    // idempotent per launch, not an allocation).
    cudaFuncSetAttribute(phase2_rnn,
                         cudaFuncAttributeMaxDynamicSharedMemorySize, SMEM2);

    dim3 g1(DOUT / 64, (B_ * T_) / 128);       // (16, 256)
    phase1_gemm<<<g1, 256>>>(x, W_in, b_in, out);
    phase2_rnn<<<NB2, 512, SMEM2>>>(W_h, periods, shifts, out);
}